// round 4
// baseline (speedup 1.0000x reference)
#include <cuda_runtime.h>

// db4 wavedec, level 4, mode='symmetric', fully fused: one CTA per (b,c) row.
// Row (8192 f32) -> SMEM; 4 DWT levels run in SMEM; details written straight
// to GMEM; approximation ping-pongs between two SMEM buffers.
//
// Output row layout (8218 f32): [cA4:518 | cD4:518 | cD3:1030 | cD2:2053 | cD1:4099]

#define L0    8192
#define O1    4099
#define O2    2053
#define O3    1030
#define O4    518
#define TOT   8218

#define NROWS   2048     // 64*32
#define NTHREADS 256

// Dynamic shared: bufA[8192] + bufB[4100]
#define SMEM_FLOATS (L0 + O1 + 1)      // 12292
#define SMEM_BYTES  (SMEM_FLOATS * 4)  // 49168

static __device__ __forceinline__ int symi(int j, int n) {
    // half-sample symmetric reflection (single reflection is sufficient here:
    // |overhang| <= 7 < n at every level)
    if (j < 0)  j = -1 - j;
    if (j >= n) j = 2 * n - 1 - j;
    return j;
}

// One DWT level. in: length n (SMEM). outA: length n_out (SMEM or GMEM).
// outD: length n_out (GMEM).
static __device__ __forceinline__ void dwt_level(
    const float* __restrict__ in, int n,
    float* __restrict__ outA,
    float* __restrict__ outD,
    int n_out)
{
    // pywt db4 rec_lo coefficients
    const float r0 =  0.23037781330885523f;
    const float r1 =  0.7148465705525415f;
    const float r2 =  0.6308807679295904f;
    const float r3 = -0.02798376941698385f;
    const float r4 = -0.18703481171888114f;
    const float r5 =  0.030841381835986965f;
    const float r6 =  0.032883011666982945f;
    const float r7 = -0.010597401784997278f;

    // fast path valid when 2i-6 >= 0 and 2i+1 <= n-1
    const int i_hi = (n - 2) >> 1;   // last interior i

    for (int i = threadIdx.x; i < n_out; i += NTHREADS) {
        float w0, w1, w2, w3, w4, w5, w6, w7;
        if (i >= 3 && i <= i_hi) {
            // 8 consecutive floats starting at even index 2i-6 -> 8B aligned
            const float2* p = reinterpret_cast<const float2*>(in + (2 * i - 6));
            float2 a = p[0], b = p[1], c = p[2], d = p[3];
            w0 = a.x; w1 = a.y; w2 = b.x; w3 = b.y;
            w4 = c.x; w5 = c.y; w6 = d.x; w7 = d.y;
        } else {
            int base = 2 * i - 6;
            w0 = in[symi(base + 0, n)];
            w1 = in[symi(base + 1, n)];
            w2 = in[symi(base + 2, n)];
            w3 = in[symi(base + 3, n)];
            w4 = in[symi(base + 4, n)];
            w5 = in[symi(base + 5, n)];
            w6 = in[symi(base + 6, n)];
            w7 = in[symi(base + 7, n)];
        }
        // cA[i] = sum_t rec_lo[t] * w[t]
        float lo = r0 * w0;
        lo = fmaf(r1, w1, lo); lo = fmaf(r2, w2, lo); lo = fmaf(r3, w3, lo);
        lo = fmaf(r4, w4, lo); lo = fmaf(r5, w5, lo); lo = fmaf(r6, w6, lo);
        lo = fmaf(r7, w7, lo);
        // cD[i] = sum_t (-1)^t * rec_lo[7-t] * w[t]
        float hi = r7 * w0;
        hi = fmaf(-r6, w1, hi); hi = fmaf( r5, w2, hi); hi = fmaf(-r4, w3, hi);
        hi = fmaf( r3, w4, hi); hi = fmaf(-r2, w5, hi); hi = fmaf( r1, w6, hi);
        hi = fmaf(-r0, w7, hi);

        outA[i] = lo;
        outD[i] = hi;
    }
}

__global__ void __launch_bounds__(NTHREADS)
wavedec_db4_l4_kernel(const float* __restrict__ x, float* __restrict__ out)
{
    extern __shared__ float smem[];
    float* bufA = smem;            // 8192 floats
    float* bufB = smem + L0;       // 4100 floats

    const int row = blockIdx.x;
    const float* xr = x + (size_t)row * L0;
    float* orow = out + (size_t)row * TOT;

    // Load the row into SMEM, vectorized
    const float4* x4 = reinterpret_cast<const float4*>(xr);
    float4* a4 = reinterpret_cast<float4*>(bufA);
    #pragma unroll 4
    for (int i = threadIdx.x; i < L0 / 4; i += NTHREADS) a4[i] = x4[i];
    __syncthreads();

    // Level 1: 8192 -> cA1(4099) in bufB, cD1 -> out[4119..]
    dwt_level(bufA, L0, bufB, orow + (O4 + O4 + O3 + O2), O1);
    __syncthreads();
    // Level 2: 4099 -> cA2(2053) in bufA, cD2 -> out[2066..]
    dwt_level(bufB, O1, bufA, orow + (O4 + O4 + O3), O2);
    __syncthreads();
    // Level 3: 2053 -> cA3(1030) in bufB, cD3 -> out[1036..]
    dwt_level(bufA, O2, bufB, orow + (O4 + O4), O3);
    __syncthreads();
    // Level 4: 1030 -> cA4(518) -> out[0..], cD4 -> out[518..]
    dwt_level(bufB, O3, orow, orow + O4, O4);
}

extern "C" void kernel_launch(void* const* d_in, const int* in_sizes, int n_in,
                              void* d_out, int out_size)
{
    (void)in_sizes; (void)n_in; (void)out_size;
    const float* x = (const float*)d_in[0];
    float* out = (float*)d_out;

    cudaFuncSetAttribute(wavedec_db4_l4_kernel,
                         cudaFuncAttributeMaxDynamicSharedMemorySize, SMEM_BYTES);
    wavedec_db4_l4_kernel<<<NROWS, NTHREADS, SMEM_BYTES>>>(x, out);
}

// round 8
// speedup vs baseline: 1.4464x; 1.4464x over previous
#include <cuda_runtime.h>

// db4 wavedec level-4 (mode='symmetric'), one CTA per (b,c) row.
// R5 resubmit (R6 infra failure): register-resident sliding windows (1 float2
// LDS per output, conflict-free odd-stride ownership), explicit symmetric
// extension in SMEM (no boundary branches), cD staged through SMEM scratch for
// coalesced GMEM stores.
//
// Output row layout (8218 f32): [cA4:518 | cD4:518 | cD3:1030 | cD2:2053 | cD1:4099]

#define L0    8192
#define O1    4099
#define O2    2053
#define O3    1030
#define O4    518
#define TOT   8218

#define NROWS 2048
#define NT    256

// SMEM layout (floats). Each buffer: [8-word left ext | body | right ext/pad].
// Pads are generous so tail-chunk overreads stay inside the allocation.
#define CAP_A 8248          // needs 8+8192+7; worst tail read idx 8235
#define CAP_B 4152          // needs 8+4099+7; worst tail read idx 4129
#define CAP_S 4100          // cD scratch (max O1)
#define SMEM_FLOATS (CAP_A + CAP_B + CAP_S)   // 16500
#define SMEM_BYTES  (SMEM_FLOATS * 4)         // 66000

// pywt db4 rec_lo
#define R0  0.23037781330885523f
#define R1  0.7148465705525415f
#define R2  0.6308807679295904f
#define R3 (-0.02798376941698385f)
#define R4 (-0.18703481171888114f)
#define R5  0.030841381835986965f
#define R6  0.032883011666982945f
#define R7 (-0.010597401784997278f)

// Fill symmetric extension of a buffer whose body (length n) sits at b+8.
// Left:  b[2+m] = body[5-m]   (m=0..5)   -> in[-6..-1]
// Right: b[8+n+m] = body[n-1-m] (m=0..6) -> in[n..n+6]
static __device__ __forceinline__ void fill_ext(float* b, int n) {
    int t = threadIdx.x;
    if (t < 6) {
        b[2 + t] = b[8 + 5 - t];
    } else if (t < 13) {
        int m = t - 6;
        b[8 + n + m] = b[8 + n - 1 - m];
    }
}

// One DWT level with register sliding window.
// ext[8+j] = in[j]; thread t owns outputs [t*T, t*T+T). Requires ceil(n_out/T) <= NT.
// Window for output i is ext[2i+2 .. 2i+9] (even start -> aligned float2).
template<int T>
static __device__ __forceinline__ void dwt_level_reg(
    const float* __restrict__ ext, int n_out,
    float* __restrict__ outA, float* __restrict__ outD)
{
    const int i0 = threadIdx.x * T;
    if (i0 >= n_out) return;

    const int base = 2 * i0 + 2;
    float2 p0 = *reinterpret_cast<const float2*>(ext + base);
    float2 p1 = *reinterpret_cast<const float2*>(ext + base + 2);
    float2 p2 = *reinterpret_cast<const float2*>(ext + base + 4);
    float w0 = p0.x, w1 = p0.y, w2 = p1.x, w3 = p1.y, w4 = p2.x, w5 = p2.y;

    if (i0 + T <= n_out) {
        #pragma unroll
        for (int j = 0; j < T; j++) {
            float2 nv = *reinterpret_cast<const float2*>(ext + base + 6 + 2 * j);
            float w6 = nv.x, w7 = nv.y;
            float lo = R0 * w0;
            lo = fmaf(R1, w1, lo); lo = fmaf(R2, w2, lo); lo = fmaf(R3, w3, lo);
            lo = fmaf(R4, w4, lo); lo = fmaf(R5, w5, lo); lo = fmaf(R6, w6, lo);
            lo = fmaf(R7, w7, lo);
            float hi = R7 * w0;
            hi = fmaf(-R6, w1, hi); hi = fmaf( R5, w2, hi); hi = fmaf(-R4, w3, hi);
            hi = fmaf( R3, w4, hi); hi = fmaf(-R2, w5, hi); hi = fmaf( R1, w6, hi);
            hi = fmaf(-R0, w7, hi);
            outA[i0 + j] = lo;
            outD[i0 + j] = hi;
            w0 = w2; w1 = w3; w2 = w4; w3 = w5; w4 = w6; w5 = w7;
        }
    } else {
        #pragma unroll
        for (int j = 0; j < T; j++) {
            float2 nv = *reinterpret_cast<const float2*>(ext + base + 6 + 2 * j);
            float w6 = nv.x, w7 = nv.y;
            float lo = R0 * w0;
            lo = fmaf(R1, w1, lo); lo = fmaf(R2, w2, lo); lo = fmaf(R3, w3, lo);
            lo = fmaf(R4, w4, lo); lo = fmaf(R5, w5, lo); lo = fmaf(R6, w6, lo);
            lo = fmaf(R7, w7, lo);
            float hi = R7 * w0;
            hi = fmaf(-R6, w1, hi); hi = fmaf( R5, w2, hi); hi = fmaf(-R4, w3, hi);
            hi = fmaf( R3, w4, hi); hi = fmaf(-R2, w5, hi); hi = fmaf( R1, w6, hi);
            hi = fmaf(-R0, w7, hi);
            if (i0 + j < n_out) {
                outA[i0 + j] = lo;
                outD[i0 + j] = hi;
            }
            w0 = w2; w1 = w3; w2 = w4; w3 = w5; w4 = w6; w5 = w7;
        }
    }
}

__global__ void __launch_bounds__(NT)
wavedec_db4_l4_kernel(const float* __restrict__ x, float* __restrict__ out)
{
    extern __shared__ float sm[];
    float* A = sm;                   // ext buffer A, body at A+8
    float* B = sm + CAP_A;           // ext buffer B, body at B+8
    float* S = sm + CAP_A + CAP_B;   // cD staging scratch

    const int row = blockIdx.x;
    const float* xr = x + (size_t)row * L0;
    float* orow = out + (size_t)row * TOT;

    // Load row into A body (32B-aligned float4)
    {
        const float4* x4 = reinterpret_cast<const float4*>(xr);
        float4* a4 = reinterpret_cast<float4*>(A + 8);
        #pragma unroll 4
        for (int i = threadIdx.x; i < L0 / 4; i += NT) a4[i] = x4[i];
    }
    __syncthreads();
    fill_ext(A, L0);
    __syncthreads();

    // Level 1: 8192 -> 4099.  ceil(4099/17)=242 chunks.
    dwt_level_reg<17>(A, O1, B + 8, S);
    __syncthreads();
    fill_ext(B, O1);
    for (int i = threadIdx.x; i < O1; i += NT)
        orow[O4 + O4 + O3 + O2 + i] = S[i];          // cD1
    __syncthreads();

    // Level 2: 4099 -> 2053.  ceil(2053/9)=229 chunks.
    dwt_level_reg<9>(B, O2, A + 8, S);
    __syncthreads();
    fill_ext(A, O2);
    for (int i = threadIdx.x; i < O2; i += NT)
        orow[O4 + O4 + O3 + i] = S[i];               // cD2
    __syncthreads();

    // Level 3: 2053 -> 1030.  ceil(1030/5)=206 chunks.
    dwt_level_reg<5>(A, O3, B + 8, S);
    __syncthreads();
    fill_ext(B, O3);
    for (int i = threadIdx.x; i < O3; i += NT)
        orow[O4 + O4 + i] = S[i];                    // cD3
    __syncthreads();

    // Level 4: 1030 -> 518. Outputs straight to GMEM (tiny, scatter OK).
    dwt_level_reg<3>(B, O4, orow, orow + O4);        // cA4, cD4
}

extern "C" void kernel_launch(void* const* d_in, const int* in_sizes, int n_in,
                              void* d_out, int out_size)
{
    (void)in_sizes; (void)n_in; (void)out_size;
    const float* x = (const float*)d_in[0];
    float* out = (float*)d_out;

    cudaFuncSetAttribute(wavedec_db4_l4_kernel,
                         cudaFuncAttributeMaxDynamicSharedMemorySize, SMEM_BYTES);
    wavedec_db4_l4_kernel<<<NROWS, NT, SMEM_BYTES>>>(x, out);
}